// round 4
// baseline (speedup 1.0000x reference)
#include <cuda_runtime.h>
#include <math.h>
#include <stdint.h>

#define N_TOK 16384
#define DIM   2048
#define NEXP  64
#define KSEL  9
#define EPS_C 0.01f
#define INV_SIG_SQRT2 45.254833995939045f
#define FLAG_TAU 5e-4f
#define FIXCAP 4096
#define FIXR 4

#define BM 128
#define CK 64                  // k elems per chunk
#define NCHUNK (DIM / CK)      // 32
#define SA 36                  // u32 stride per row/expert (bank = (4g+t)&31: conflict-free)
#define ARR (128 * SA)         // 4608 u32 per split array
#define AH_OFF 0
#define AL_OFF ARR
#define BH_OFF (2 * ARR)
#define BL_OFF (3 * ARR)
#define BUFU (4 * ARR)         // 18432 u32 per buffer
#define SMEM_BYTES (2 * BUFU * 4)   // 147456 B
#define WCHUNK (2 * ARR)       // 9216 u32 pre-split weights per chunk
#define ACC_STRIDE 133         // 133 mod 32 = 5, coprime -> conflict-free row reads

__device__ __align__(16) uint32_t g_wbuf[(size_t)NCHUNK * WCHUNK];
__device__ int g_flagcnt;
__device__ int g_flags[FIXCAP];

// pack: low16 = bf16(a), high16 = bf16(b)
__device__ __forceinline__ uint32_t pack2(float a, float b) {
    uint32_t r;
    asm("cvt.rn.bf16x2.f32 %0, %1, %2;" : "=r"(r) : "f"(b), "f"(a));
    return r;
}
__device__ __forceinline__ float lo_f(uint32_t u) { return __uint_as_float(u << 16); }
__device__ __forceinline__ float hi_f(uint32_t u) { return __uint_as_float(u & 0xffff0000u); }

__device__ __forceinline__ void hmma(float* c, const uint32_t* a, uint32_t b0, uint32_t b1) {
    asm("mma.sync.aligned.m16n8k16.row.col.f32.bf16.bf16.f32 "
        "{%0,%1,%2,%3}, {%4,%5,%6,%7}, {%8,%9}, {%0,%1,%2,%3};"
        : "+f"(c[0]), "+f"(c[1]), "+f"(c[2]), "+f"(c[3])
        : "r"(a[0]), "r"(a[1]), "r"(a[2]), "r"(a[3]), "r"(b0), "r"(b1));
}

// ---------------- weight prep: fp32 -> bf16 hi/lo in smem-image layout ----------------
extern "C" __global__ void prep_w_kernel(const float* __restrict__ Wr,
                                         const float* __restrict__ Wn) {
    int idx = blockIdx.x * 256 + threadIdx.x;     // 0..131071
    if (idx == 0) g_flagcnt = 0;
    int e  = idx & 127;                            // 0-63 Wr, 64-127 Wn
    int kp = (idx >> 7) & 31;                      // k-pair within chunk
    int c  = idx >> 12;                            // chunk
    int k0 = c * CK + 2 * kp;
    const float* W = (e < 64) ? Wr : Wn;
    int ee = e & 63;
    float w0 = W[(size_t)k0 * NEXP + ee];
    float w1 = W[(size_t)(k0 + 1) * NEXP + ee];
    uint32_t hi = pack2(w0, w1);
    uint32_t lo = pack2(w0 - lo_f(hi), w1 - hi_f(hi));
    uint32_t* dst = g_wbuf + (size_t)c * WCHUNK + e * SA + kp;
    dst[0]   = hi;
    dst[ARR] = lo;
}

// ---------------- fused router: 3-term bf16 HMMA + validated epilogue ----------------
extern "C" __global__ void __launch_bounds__(256, 1)
router_kernel(const float* __restrict__ x,  const float* __restrict__ br,
              const float* __restrict__ bn, const float* __restrict__ neps,
              const float* __restrict__ gum, float* __restrict__ out)
{
    extern __shared__ uint32_t sm[];
    const int tid  = threadIdx.x;
    const int wid  = tid >> 5;
    const int lane = tid & 31;
    const int g    = lane >> 2;
    const int t    = lane & 3;
    const int R    = (wid & 3) * 32;     // m-band base row
    const int E    = (wid >> 2) * 64;    // n-half base col
    const int row0 = blockIdx.x * BM;

    // staging mapping: 2 threads per row (sr), each owns 32 k-elems (sh half)
    const int sr = tid >> 1, sh = tid & 1;
    const float* xrow = x + (size_t)(row0 + sr) * DIM + sh * 32;

    float acc[2][8][4];
    #pragma unroll
    for (int mi = 0; mi < 2; mi++)
        #pragma unroll
        for (int j = 0; j < 8; j++)
            #pragma unroll
            for (int q = 0; q < 4; q++) acc[mi][j][q] = 0.f;

    float4 xa[8], wb[9];

    // ---- prologue: stage chunk 0 into buf 0 ----
    {
        const float4* wsrc = (const float4*)(g_wbuf);
        #pragma unroll
        for (int j = 0; j < 9; j++) wb[j] = wsrc[tid + 256 * j];
        #pragma unroll
        for (int q = 0; q < 8; q++) xa[q] = *(const float4*)(xrow + 4 * q);
        float4* bdst = (float4*)(sm + BH_OFF);
        #pragma unroll
        for (int j = 0; j < 9; j++) bdst[tid + 256 * j] = wb[j];
        #pragma unroll
        for (int q = 0; q < 8; q++) {
            uint32_t h0 = pack2(xa[q].x, xa[q].y), h1 = pack2(xa[q].z, xa[q].w);
            uint32_t l0 = pack2(xa[q].x - lo_f(h0), xa[q].y - hi_f(h0));
            uint32_t l1 = pack2(xa[q].z - lo_f(h1), xa[q].w - hi_f(h1));
            int kp = sh * 16 + 2 * q;
            *(uint2*)(sm + AH_OFF + sr * SA + kp) = make_uint2(h0, h1);
            *(uint2*)(sm + AL_OFF + sr * SA + kp) = make_uint2(l0, l1);
        }
    }
    __syncthreads();

    #pragma unroll 1
    for (int c = 0; c < NCHUNK; ++c) {
        const int p = c & 1;
        const bool more = (c + 1 < NCHUNK);
        if (more) {
            const float4* wsrc = (const float4*)(g_wbuf + (size_t)(c + 1) * WCHUNK);
            #pragma unroll
            for (int j = 0; j < 9; j++) wb[j] = wsrc[tid + 256 * j];
            #pragma unroll
            for (int q = 0; q < 8; q++)
                xa[q] = *(const float4*)(xrow + (c + 1) * CK + 4 * q);
        }
        // ---- compute chunk c from buf p ----
        {
            const uint32_t* buf = sm + p * BUFU;
            #pragma unroll
            for (int ks = 0; ks < 4; ks++) {
                const int kp = 8 * ks;
                uint32_t ah[2][4], al[2][4];
                #pragma unroll
                for (int mi = 0; mi < 2; mi++) {
                    const uint32_t* pa = buf + AH_OFF + (R + mi * 16 + g) * SA + kp + t;
                    ah[mi][0] = pa[0]; ah[mi][1] = pa[8 * SA];
                    ah[mi][2] = pa[4]; ah[mi][3] = pa[8 * SA + 4];
                    const uint32_t* pl = buf + AL_OFF + (R + mi * 16 + g) * SA + kp + t;
                    al[mi][0] = pl[0]; al[mi][1] = pl[8 * SA];
                    al[mi][2] = pl[4]; al[mi][3] = pl[8 * SA + 4];
                }
                #pragma unroll
                for (int j = 0; j < 8; j++) {
                    const uint32_t* pb = buf + BH_OFF + (E + 8 * j + g) * SA + kp + t;
                    uint32_t bh0 = pb[0], bh1 = pb[4];
                    const uint32_t* pbl = buf + BL_OFF + (E + 8 * j + g) * SA + kp + t;
                    uint32_t bl0 = pbl[0], bl1 = pbl[4];
                    #pragma unroll
                    for (int mi = 0; mi < 2; mi++) {
                        hmma(acc[mi][j], ah[mi], bh0, bh1);   // hi*hi
                        hmma(acc[mi][j], al[mi], bh0, bh1);   // lo*hi
                        hmma(acc[mi][j], ah[mi], bl0, bl1);   // hi*lo
                    }
                }
            }
        }
        if (more) {
            __syncthreads();
            uint32_t* buf = sm + (1 - p) * BUFU;
            float4* bdst = (float4*)(buf + BH_OFF);
            #pragma unroll
            for (int j = 0; j < 9; j++) bdst[tid + 256 * j] = wb[j];
            #pragma unroll
            for (int q = 0; q < 8; q++) {
                uint32_t h0 = pack2(xa[q].x, xa[q].y), h1 = pack2(xa[q].z, xa[q].w);
                uint32_t l0 = pack2(xa[q].x - lo_f(h0), xa[q].y - hi_f(h0));
                uint32_t l1 = pack2(xa[q].z - lo_f(h1), xa[q].w - hi_f(h1));
                int kp = sh * 16 + 2 * q;
                *(uint2*)(buf + AH_OFF + sr * SA + kp) = make_uint2(h0, h1);
                *(uint2*)(buf + AL_OFF + sr * SA + kp) = make_uint2(l0, l1);
            }
            __syncthreads();
        }
    }

    // ---- write fragments to smem overlay (buf0 region only: 68.6KB < 72KB) ----
    float* acc_s  = (float*)sm;
    float* imp_s  = acc_s + BM * ACC_STRIDE;
    float* load_s = imp_s + 64;
    // last compute read buf1; overlay targets buf0, last read at chunk 30 (synced) -> safe
    #pragma unroll
    for (int mi = 0; mi < 2; mi++)
        #pragma unroll
        for (int j = 0; j < 8; j++) {
            int row = R + mi * 16 + g;
            int col = E + 8 * j + 2 * t;
            acc_s[row * ACC_STRIDE + col]           = acc[mi][j][0];
            acc_s[row * ACC_STRIDE + col + 1]       = acc[mi][j][1];
            acc_s[(row + 8) * ACC_STRIDE + col]     = acc[mi][j][2];
            acc_s[(row + 8) * ACC_STRIDE + col + 1] = acc[mi][j][3];
        }
    if (tid < 64) { imp_s[tid] = 0.f; load_s[tid] = 0.f; }
    __syncthreads();

    // ---- per-row epilogue (round-1 validated) + boundary flagging ----
    if (tid < BM) {
        const int grow = row0 + tid;
        float* rowraw = acc_s + tid * ACC_STRIDE;   // cols 0..63  : raw logits
        float* rowns  = rowraw + 64;                // cols 64..127: pre -> noisy
        const float* eps_row = neps + (size_t)grow * NEXP;
        const float* g_row   = gum  + (size_t)grow * NEXP;

        float stdv[NEXP];
        #pragma unroll
        for (int e = 0; e < NEXP; e++) {
            float raw = rowraw[e] + br[e];
            rowraw[e] = raw;
            float pre = rowns[e] + bn[e];
            float sd = fmaxf(pre, 0.f) + log1pf(expf(-fabsf(pre))) + EPS_C;
            stdv[e] = sd;
            rowns[e] = fmaf(eps_row[e], sd, raw);
        }

        unsigned long long taken = 0ULL;
        float thr = 0.f;
        for (int tsel = 0; tsel < KSEL; tsel++) {
            float m = -INFINITY; int mi = 0;
            for (int e = 0; e < NEXP; e++) {
                float v = rowns[e];
                if (!((taken >> e) & 1ULL) && v > m) { m = v; mi = e; }
            }
            taken |= (1ULL << mi);
            thr = m;
        }
        // 10th largest -> gap; flag boundary rows for exact fixup
        float m10 = -INFINITY;
        for (int e = 0; e < NEXP; e++) {
            float v = rowns[e];
            if (!((taken >> e) & 1ULL) && v > m10) m10 = v;
        }
        if (thr - m10 < FLAG_TAU) {
            int ix = atomicAdd(&g_flagcnt, 1);
            if (ix < FIXCAP) g_flags[ix] = grow;
        }

        float m1 = -INFINITY, m2 = -INFINITY, m3 = -INFINITY;
        #pragma unroll
        for (int e = 0; e < NEXP; e++) {
            float nz = rowns[e];
            m1 = fmaxf(m1, nz);
            m2 = fmaxf(m2, nz + g_row[e]);
            m3 = fmaxf(m3, rowraw[e]);
        }
        float s1 = 0.f, s2 = 0.f, s3 = 0.f;
        #pragma unroll
        for (int e = 0; e < NEXP; e++) {
            float nz = rowns[e];
            s1 += expf(nz - m1);
            s2 += expf(nz + g_row[e] - m2);
            s3 += expf(rowraw[e] - m3);
        }
        float i1 = 1.f / s1, i2 = 1.f / s2, i3 = 1.f / s3;

        float* om  = out + (size_t)grow * NEXP;
        float* orp = out + (size_t)N_TOK * NEXP + (size_t)grow * NEXP;
        #pragma unroll
        for (int e = 0; e < NEXP; e++) {
            float nz  = rowns[e];
            float raw = rowraw[e];
            float ms  = expf(nz + g_row[e] - m2) * i2;
            float hard = ((taken >> e) & 1ULL) ? 1.f : 0.f;
            om[e]  = (hard - ms) + ms;
            orp[e] = expf(nz - m1) * i1;
            float imp = expf(raw - m3) * i3;
            float z = (thr - raw) / stdv[e];
            float ld = 0.5f * (1.f - erff(z * INV_SIG_SQRT2));
            #pragma unroll
            for (int o = 16; o; o >>= 1) {
                imp += __shfl_xor_sync(0xffffffffu, imp, o);
                ld  += __shfl_xor_sync(0xffffffffu, ld,  o);
            }
            if ((tid & 31) == 0) {
                atomicAdd(&imp_s[e], imp);
                atomicAdd(&load_s[e], ld);
            }
        }
    }
    __syncthreads();
    if (tid < 64) {
        atomicAdd(out + 2 * (size_t)N_TOK * NEXP + tid,        imp_s[tid]);
        atomicAdd(out + 2 * (size_t)N_TOK * NEXP + NEXP + tid, load_s[tid]);
    }
}

// ---------------- exact fp32 fixup for top-k boundary rows ----------------
extern "C" __global__ void __launch_bounds__(256)
fixup_kernel(const float* __restrict__ x,  const float* __restrict__ Wr,
             const float* __restrict__ br, const float* __restrict__ Wn,
             const float* __restrict__ bn, const float* __restrict__ neps,
             float* __restrict__ out)
{
    __shared__ float xs[FIXR][DIM];
    __shared__ float lg[FIXR][128];   // 0..63 raw dot, 64..127 noise dot
    const int tid = threadIdx.x;
    int cnt = g_flagcnt; if (cnt > FIXCAP) cnt = FIXCAP;
    const int ngrp = (cnt + FIXR - 1) / FIXR;

    for (int grp = blockIdx.x; grp < ngrp; grp += gridDim.x) {
        const int nr = (cnt - grp * FIXR < FIXR) ? (cnt - grp * FIXR) : FIXR;
        for (int r = 0; r < nr; r++) {
            const float4* xr = (const float4*)(x + (size_t)g_flags[grp * FIXR + r] * DIM);
            for (int i = tid; i < DIM / 4; i += 256) ((float4*)xs[r])[i] = xr[i];
        }
        __syncthreads();
        if (tid < 128) {
            const float* W = (tid & 64) ? Wn : Wr;
            const int ee = tid & 63;
            float a[FIXR] = {0.f, 0.f, 0.f, 0.f};
            #pragma unroll 4
            for (int k = 0; k < DIM; k++) {
                float w = W[(size_t)k * NEXP + ee];
                #pragma unroll
                for (int r = 0; r < FIXR; r++) a[r] = fmaf(xs[r][k], w, a[r]);
            }
            for (int r = 0; r < nr; r++) lg[r][tid] = a[r];
        }
        __syncthreads();
        if (tid < nr) {
            const int row = g_flags[grp * FIXR + tid];
            const float* eps_row = neps + (size_t)row * NEXP;
            float ns[NEXP];
            #pragma unroll
            for (int e = 0; e < NEXP; e++) {
                float raw = lg[tid][e] + br[e];
                float pre = lg[tid][64 + e] + bn[e];
                float sd = fmaxf(pre, 0.f) + log1pf(expf(-fabsf(pre))) + EPS_C;
                ns[e] = fmaf(eps_row[e], sd, raw);
            }
            unsigned long long taken = 0ULL;
            for (int tsel = 0; tsel < KSEL; tsel++) {
                float m = -INFINITY; int mi = 0;
                for (int e = 0; e < NEXP; e++) {
                    float v = ns[e];
                    if (!((taken >> e) & 1ULL) && v > m) { m = v; mi = e; }
                }
                taken |= (1ULL << mi);
            }
            float* om = out + (size_t)row * NEXP;
            for (int e = 0; e < NEXP; e++) {
                float v = om[e];
                bool ho = v > 0.5f;
                bool hn = (taken >> e) & 1ULL;
                if (ho != hn) om[e] = v + (hn ? 1.f : -1.f);
            }
        }
        __syncthreads();
    }
}

extern "C" void kernel_launch(void* const* d_in, const int* in_sizes, int n_in,
                              void* d_out, int out_size)
{
    const float* x    = (const float*)d_in[0];
    const float* Wr   = (const float*)d_in[1];
    const float* br   = (const float*)d_in[2];
    const float* Wn   = (const float*)d_in[3];
    const float* bn   = (const float*)d_in[4];
    const float* neps = (const float*)d_in[5];
    const float* gum  = (const float*)d_in[6];
    float* out = (float*)d_out;

    cudaMemsetAsync(out + 2 * (size_t)N_TOK * NEXP, 0, 2 * NEXP * sizeof(float));
    prep_w_kernel<<<512, 256>>>(Wr, Wn);

    cudaFuncSetAttribute(router_kernel,
                         cudaFuncAttributeMaxDynamicSharedMemorySize, SMEM_BYTES);
    router_kernel<<<N_TOK / BM, 256, SMEM_BYTES>>>(x, br, bn, neps, gum, out);
    fixup_kernel<<<64, 256>>>(x, Wr, br, Wn, bn, neps, out);
}

// round 5
// speedup vs baseline: 1.7465x; 1.7465x over previous
#include <cuda_runtime.h>
#include <math.h>
#include <stdint.h>

#define N_TOK 16384
#define DIM   2048
#define NEXP  64
#define KSEL  9
#define EPS_C 0.01f
#define INV_SIG_SQRT2 45.254833995939045f

#define BM 64
#define BK 32
#define NCHUNK (DIM / BK)        // 64
#define XST 68                   // x_sT row stride (u32), 16B-aligned loads
#define WST 128                  // w_s row stride (u32)
#define BUFU (BK * XST + BK * WST)   // 6272 u32 per buffer
#define SMEM_BYTES (2 * BUFU * 4)    // 50176 B

// weight image: [chunk][kk][128 cols] fp32 (cols 0-63 Wr, 64-127 Wn) = 1 MB
__device__ __align__(16) float g_wimg[(size_t)NCHUNK * BK * 128];
// logits scratch: [row][128] (0-63 raw dot, 64-127 noise-pre dot) = 8 MB
__device__ __align__(16) float g_lg[(size_t)N_TOK * 128];

__device__ __forceinline__ unsigned long long pack_dup(float a) {
    unsigned long long r;
    unsigned ai = __float_as_uint(a);
    asm("mov.b64 %0, {%1, %1};" : "=l"(r) : "r"(ai));
    return r;
}

// ---------------- prep: repack Wr||Wn into chunked image ----------------
extern "C" __global__ void prep_w_kernel(const float* __restrict__ Wr,
                                         const float* __restrict__ Wn) {
    int idx = blockIdx.x * 256 + threadIdx.x;   // 0..262143
    int col = idx & 127;
    int k   = idx >> 7;                          // global k (chunk*32 + kk)
    const float* W = (col < 64) ? Wr : Wn;
    g_wimg[idx] = W[(size_t)k * NEXP + (col & 63)];
}

// ---------------- GEMM: fp32 FFMA2, 64 rows x 128 cols per CTA ----------------
extern "C" __global__ void __launch_bounds__(256, 2)
gemm_kernel(const float* __restrict__ x)
{
    extern __shared__ float smf[];
    const int tid = threadIdx.x;
    const int ty  = tid >> 4;      // 0..15 -> rows 4ty..4ty+3
    const int tx  = tid & 15;      // col pairs (2tx+32j, 2tx+32j+1)
    const int row0 = blockIdx.x * BM;

    // x staging map: q = k-quad, r = row
    const int q = tid & 7, r = tid >> 3;
    const float* xb0 = x + (size_t)(row0 + r)      * DIM + 4 * q;
    const float* xb1 = x + (size_t)(row0 + r + 32) * DIM + 4 * q;

    unsigned long long acc[4][4];
    #pragma unroll
    for (int i = 0; i < 4; i++)
        #pragma unroll
        for (int j = 0; j < 4; j++) acc[i][j] = 0ULL;

    float4 wb[4], xv0, xv1;

    // ---- stage chunk 0 into buffer 0 ----
    {
        const float4* ws = (const float4*)g_wimg;
        #pragma unroll
        for (int j = 0; j < 4; j++) wb[j] = ws[tid + 256 * j];
        xv0 = *(const float4*)xb0;
        xv1 = *(const float4*)xb1;
        float4* wd = (float4*)(smf + BK * XST);
        #pragma unroll
        for (int j = 0; j < 4; j++) wd[tid + 256 * j] = wb[j];
        #pragma unroll
        for (int j = 0; j < 4; j++) {
            smf[(4 * q + j) * XST + r]      = (&xv0.x)[j];
            smf[(4 * q + j) * XST + r + 32] = (&xv1.x)[j];
        }
    }
    __syncthreads();

    #pragma unroll 1
    for (int c = 0; c < NCHUNK; c++) {
        float* buf = smf + (c & 1) * BUFU;
        const bool more = (c + 1 < NCHUNK);
        if (more) {
            const float4* ws = (const float4*)(g_wimg + (size_t)(c + 1) * (BK * 128));
            #pragma unroll
            for (int j = 0; j < 4; j++) wb[j] = ws[tid + 256 * j];
            xv0 = *(const float4*)(xb0 + (c + 1) * BK);
            xv1 = *(const float4*)(xb1 + (c + 1) * BK);
        }
        const float* xs = buf;
        const float* ws_ = buf + BK * XST;
        #pragma unroll 8
        for (int kk = 0; kk < BK; kk++) {
            float4 av = *(const float4*)(xs + kk * XST + 4 * ty);
            unsigned long long b2[4];
            #pragma unroll
            for (int j = 0; j < 4; j++)
                b2[j] = *(const unsigned long long*)(ws_ + kk * WST + 2 * tx + 32 * j);
            unsigned long long a2[4];
            a2[0] = pack_dup(av.x); a2[1] = pack_dup(av.y);
            a2[2] = pack_dup(av.z); a2[3] = pack_dup(av.w);
            #pragma unroll
            for (int i = 0; i < 4; i++)
                #pragma unroll
                for (int j = 0; j < 4; j++)
                    asm("fma.rn.f32x2 %0, %1, %2, %0;"
                        : "+l"(acc[i][j]) : "l"(a2[i]), "l"(b2[j]));
        }
        if (more) {
            __syncthreads();
            float* nbuf = smf + ((c + 1) & 1) * BUFU;
            float4* wd = (float4*)(nbuf + BK * XST);
            #pragma unroll
            for (int j = 0; j < 4; j++) wd[tid + 256 * j] = wb[j];
            #pragma unroll
            for (int j = 0; j < 4; j++) {
                nbuf[(4 * q + j) * XST + r]      = (&xv0.x)[j];
                nbuf[(4 * q + j) * XST + r + 32] = (&xv1.x)[j];
            }
            __syncthreads();
        }
    }

    // ---- write logits (pairs are adjacent cols -> STG.64, coalesced) ----
    #pragma unroll
    for (int i = 0; i < 4; i++)
        #pragma unroll
        for (int j = 0; j < 4; j++)
            *(unsigned long long*)(g_lg + (size_t)(row0 + 4 * ty + i) * 128
                                   + 2 * tx + 32 * j) = acc[i][j];
}

// ---------------- epilogue: warp per row, 2 experts per lane ----------------
__device__ __forceinline__ float wmax(float v) {
    #pragma unroll
    for (int o = 16; o; o >>= 1) v = fmaxf(v, __shfl_xor_sync(0xffffffffu, v, o));
    return v;
}
__device__ __forceinline__ float wsum(float v) {
    #pragma unroll
    for (int o = 16; o; o >>= 1) v += __shfl_xor_sync(0xffffffffu, v, o);
    return v;
}

extern "C" __global__ void __launch_bounds__(256)
epi_kernel(const float* __restrict__ br,  const float* __restrict__ bn,
           const float* __restrict__ neps, const float* __restrict__ gum,
           float* __restrict__ out)
{
    __shared__ float imp_s[64], load_s[64];
    const int tid = threadIdx.x;
    const int wid = tid >> 5;
    const int lane = tid & 31;
    if (tid < 64) { imp_s[tid] = 0.f; load_s[tid] = 0.f; }
    __syncthreads();

    const int e0 = lane, e1 = lane + 32;
    const float br0 = br[e0], br1 = br[e1];
    const float bn0 = bn[e0], bn1 = bn[e1];
    float impa0 = 0.f, impa1 = 0.f, lda0 = 0.f, lda1 = 0.f;

    const int wg = blockIdx.x * 8 + wid;        // 0..2047
    #pragma unroll 1
    for (int rr = 0; rr < 8; rr++) {
        const int row = wg * 8 + rr;
        const float* L = g_lg + (size_t)row * 128;
        float raw0 = L[e0] + br0,      raw1 = L[e1] + br1;
        float pre0 = L[64 + e0] + bn0, pre1 = L[64 + e1] + bn1;
        float sd0 = fmaxf(pre0, 0.f) + log1pf(expf(-fabsf(pre0))) + EPS_C;
        float sd1 = fmaxf(pre1, 0.f) + log1pf(expf(-fabsf(pre1))) + EPS_C;
        float nz0 = fmaf(neps[(size_t)row * NEXP + e0], sd0, raw0);
        float nz1 = fmaf(neps[(size_t)row * NEXP + e1], sd1, raw1);
        float g0 = gum[(size_t)row * NEXP + e0];
        float g1 = gum[(size_t)row * NEXP + e1];

        // ---- top-9 via 9 warp argmax reductions (tie -> lower index) ----
        float w0 = nz0, w1 = nz1, thr = 0.f;
        float h0 = 0.f, h1 = 0.f;
        #pragma unroll 1
        for (int t = 0; t < KSEL; t++) {
            float v; int id;
            if (w0 >= w1) { v = w0; id = e0; } else { v = w1; id = e1; }
            #pragma unroll
            for (int o = 16; o; o >>= 1) {
                float ov = __shfl_xor_sync(0xffffffffu, v, o);
                int   oi = __shfl_xor_sync(0xffffffffu, id, o);
                if (ov > v || (ov == v && oi < id)) { v = ov; id = oi; }
            }
            thr = v;
            if (id == e0) { w0 = -INFINITY; h0 = 1.f; }
            if (id == e1) { w1 = -INFINITY; h1 = 1.f; }
        }

        // ---- softmax maxes / sums (exp computed once) ----
        float m1 = wmax(fmaxf(nz0, nz1));
        float m2 = wmax(fmaxf(nz0 + g0, nz1 + g1));
        float m3 = wmax(fmaxf(raw0, raw1));
        float E10 = expf(nz0 - m1),      E11 = expf(nz1 - m1);
        float E20 = expf(nz0 + g0 - m2), E21 = expf(nz1 + g1 - m2);
        float E30 = expf(raw0 - m3),     E31 = expf(raw1 - m3);
        float i1 = 1.f / wsum(E10 + E11);
        float i2 = 1.f / wsum(E20 + E21);
        float i3 = 1.f / wsum(E30 + E31);

        float ms0 = E20 * i2, ms1 = E21 * i2;
        float* om  = out + (size_t)row * NEXP;
        float* orp = out + (size_t)N_TOK * NEXP + (size_t)row * NEXP;
        om[e0]  = (h0 - ms0) + ms0;
        om[e1]  = (h1 - ms1) + ms1;
        orp[e0] = E10 * i1;
        orp[e1] = E11 * i1;

        impa0 += E30 * i3;
        impa1 += E31 * i3;
        float z0 = (thr - raw0) / sd0, z1 = (thr - raw1) / sd1;
        lda0 += 0.5f * (1.f - erff(z0 * INV_SIG_SQRT2));
        lda1 += 0.5f * (1.f - erff(z1 * INV_SIG_SQRT2));
    }

    atomicAdd(&imp_s[e0], impa0);
    atomicAdd(&imp_s[e1], impa1);
    atomicAdd(&load_s[e0], lda0);
    atomicAdd(&load_s[e1], lda1);
    __syncthreads();
    if (tid < 64) {
        atomicAdd(out + 2 * (size_t)N_TOK * NEXP + tid,        imp_s[tid]);
        atomicAdd(out + 2 * (size_t)N_TOK * NEXP + NEXP + tid, load_s[tid]);
    }
}

extern "C" void kernel_launch(void* const* d_in, const int* in_sizes, int n_in,
                              void* d_out, int out_size)
{
    const float* x    = (const float*)d_in[0];
    const float* Wr   = (const float*)d_in[1];
    const float* br   = (const float*)d_in[2];
    const float* Wn   = (const float*)d_in[3];
    const float* bn   = (const float*)d_in[4];
    const float* neps = (const float*)d_in[5];
    const float* gum  = (const float*)d_in[6];
    float* out = (float*)d_out;

    cudaMemsetAsync(out + 2 * (size_t)N_TOK * NEXP, 0, 2 * NEXP * sizeof(float));
    prep_w_kernel<<<1024, 256>>>(Wr, Wn);

    cudaFuncSetAttribute(gemm_kernel,
                         cudaFuncAttributeMaxDynamicSharedMemorySize, SMEM_BYTES);
    gemm_kernel<<<N_TOK / BM, 256, SMEM_BYTES>>>(x);

    epi_kernel<<<N_TOK / 64, 256>>>(br, bn, neps, gum, out);
}

// round 6
// speedup vs baseline: 2.1632x; 1.2386x over previous
#include <cuda_runtime.h>
#include <math.h>
#include <stdint.h>

#define N_TOK 16384
#define DIM   2048
#define NEXP  64
#define KSEL  9
#define EPS_C 0.01f
#define INV_SIG_SQRT2 45.254833995939045f

#define BM 128
#define BK 32
#define NCHUNK (DIM / BK)          // 64
#define NSTAGE 4
#define XTS 36                     // x smem row stride (u32): 144B, 16B-aligned, bank-shift 4
#define XTILE (BM * XTS)           // 4608 u32
#define WTILE (BK * 128)           // 4096 u32
#define STAGEU (XTILE + WTILE)     // 8704 u32 = 34816 B
#define SMEM_BYTES (NSTAGE * STAGEU * 4)   // 139264 B

// logits scratch: [row][128] (0-63 raw dot, 64-127 noise-pre dot) = 8 MB
__device__ __align__(16) float g_lg[(size_t)N_TOK * 128];

__device__ __forceinline__ unsigned long long pack_dup(float a) {
    unsigned long long r;
    unsigned ai = __float_as_uint(a);
    asm("mov.b64 %0, {%1, %1};" : "=l"(r) : "r"(ai));
    return r;
}
__device__ __forceinline__ uint32_t smem_u32(const void* p) {
    uint32_t a;
    asm("{ .reg .u64 t; cvta.to.shared.u64 t, %1; cvt.u32.u64 %0, t; }"
        : "=r"(a) : "l"(p));
    return a;
}
__device__ __forceinline__ void cp16(uint32_t dst, const void* src) {
    asm volatile("cp.async.ca.shared.global [%0], [%1], 16;"
                 :: "r"(dst), "l"(src) : "memory");
}

// ---------------- GEMM: fp32 FFMA2, 128x128 per CTA, 4-stage cp.async ----------------
extern "C" __global__ void __launch_bounds__(256, 1)
gemm_kernel(const float* __restrict__ x, const float* __restrict__ Wr,
            const float* __restrict__ Wn)
{
    extern __shared__ uint32_t smu[];
    const uint32_t sbase = smem_u32(smu);
    const int tid = threadIdx.x;
    const int ty  = tid >> 4;        // rows 8ty..8ty+7
    const int tx  = tid & 15;        // col pairs 2tx+32j
    const int row0 = blockIdx.x * BM;

    // cp.async segment maps (fixed per thread)
    const int xr = tid >> 3, xseg = tid & 7;         // +64 rows per i
    const int wk = tid >> 5, wq = tid & 31;          // +8 kk per i
    const float* xsrc0 = x + (size_t)(row0 + xr) * DIM + xseg * 4;
    const int wcol = wq * 4;
    const float* wsrcbase = (wcol < 64) ? (Wr + wcol) : (Wn + wcol - 64);

    unsigned long long acc[8][4];
    #pragma unroll
    for (int i = 0; i < 8; i++)
        #pragma unroll
        for (int j = 0; j < 4; j++) acc[i][j] = 0ULL;

    // ---- issue loads for a chunk into stage buffer ----
    auto issue = [&](int c) {
        uint32_t buf = sbase + (uint32_t)((c & (NSTAGE - 1)) * STAGEU * 4);
        #pragma unroll
        for (int i = 0; i < 4; i++) {
            int row = xr + 32 * i;
            cp16(buf + (uint32_t)((row * XTS + xseg * 4) * 4),
                 xsrc0 + (size_t)(32 * i) * DIM + c * BK);
        }
        #pragma unroll
        for (int i = 0; i < 4; i++) {
            int kk = wk + 8 * i;
            cp16(buf + (uint32_t)((XTILE + kk * 128 + wcol) * 4),
                 wsrcbase + (size_t)(c * BK + kk) * NEXP);
        }
    };

    // prologue: stages 0..2
    #pragma unroll
    for (int p = 0; p < NSTAGE - 1; p++) {
        issue(p);
        asm volatile("cp.async.commit_group;" ::: "memory");
    }

    #pragma unroll 1
    for (int c = 0; c < NCHUNK; c++) {
        asm volatile("cp.async.wait_group %0;" :: "n"(NSTAGE - 2) : "memory");
        __syncthreads();
        if (c + NSTAGE - 1 < NCHUNK) issue(c + NSTAGE - 1);
        asm volatile("cp.async.commit_group;" ::: "memory");

        const uint32_t* buf = smu + (c & (NSTAGE - 1)) * STAGEU;
        const float* xs = (const float*)buf;
        const float* ws = (const float*)(buf + XTILE);
        #pragma unroll 4
        for (int kk = 0; kk < BK; kk++) {
            unsigned long long b2[4];
            #pragma unroll
            for (int j = 0; j < 4; j++)
                b2[j] = *(const unsigned long long*)(ws + kk * 128 + 2 * tx + 32 * j);
            unsigned long long a2[8];
            #pragma unroll
            for (int i = 0; i < 8; i++)
                a2[i] = pack_dup(xs[(8 * ty + i) * XTS + kk]);
            #pragma unroll
            for (int i = 0; i < 8; i++)
                #pragma unroll
                for (int j = 0; j < 4; j++)
                    asm("fma.rn.f32x2 %0, %1, %2, %0;"
                        : "+l"(acc[i][j]) : "l"(a2[i]), "l"(b2[j]));
        }
        __syncthreads();
    }

    // ---- write logits (adjacent col pairs -> STG.64, coalesced per warp) ----
    #pragma unroll
    for (int i = 0; i < 8; i++)
        #pragma unroll
        for (int j = 0; j < 4; j++)
            *(unsigned long long*)(g_lg + (size_t)(row0 + 8 * ty + i) * 128
                                   + 2 * tx + 32 * j) = acc[i][j];
}

// ---------------- epilogue: warp per row, 2 experts per lane ----------------
__device__ __forceinline__ float wmax(float v) {
    #pragma unroll
    for (int o = 16; o; o >>= 1) v = fmaxf(v, __shfl_xor_sync(0xffffffffu, v, o));
    return v;
}
__device__ __forceinline__ float wsum(float v) {
    #pragma unroll
    for (int o = 16; o; o >>= 1) v += __shfl_xor_sync(0xffffffffu, v, o);
    return v;
}

extern "C" __global__ void __launch_bounds__(256)
epi_kernel(const float* __restrict__ br,  const float* __restrict__ bn,
           const float* __restrict__ neps, const float* __restrict__ gum,
           float* __restrict__ out)
{
    __shared__ float imp_s[64], load_s[64];
    const int tid = threadIdx.x;
    const int wid = tid >> 5;
    const int lane = tid & 31;
    if (tid < 64) { imp_s[tid] = 0.f; load_s[tid] = 0.f; }
    __syncthreads();

    const int e0 = lane, e1 = lane + 32;
    const float br0 = br[e0], br1 = br[e1];
    const float bn0 = bn[e0], bn1 = bn[e1];
    float impa0 = 0.f, impa1 = 0.f, lda0 = 0.f, lda1 = 0.f;

    const int wg = blockIdx.x * 8 + wid;        // 0..2047
    #pragma unroll 1
    for (int rr = 0; rr < 8; rr++) {
        const int row = wg * 8 + rr;
        const float* L = g_lg + (size_t)row * 128;
        float raw0 = L[e0] + br0,      raw1 = L[e1] + br1;
        float pre0 = L[64 + e0] + bn0, pre1 = L[64 + e1] + bn1;
        float sd0 = fmaxf(pre0, 0.f) + log1pf(expf(-fabsf(pre0))) + EPS_C;
        float sd1 = fmaxf(pre1, 0.f) + log1pf(expf(-fabsf(pre1))) + EPS_C;
        float nz0 = fmaf(neps[(size_t)row * NEXP + e0], sd0, raw0);
        float nz1 = fmaf(neps[(size_t)row * NEXP + e1], sd1, raw1);
        float g0 = gum[(size_t)row * NEXP + e0];
        float g1 = gum[(size_t)row * NEXP + e1];

        // ---- top-9 via 9 warp argmax reductions (tie -> lower index) ----
        float w0 = nz0, w1 = nz1, thr = 0.f;
        float h0 = 0.f, h1 = 0.f;
        #pragma unroll 1
        for (int t = 0; t < KSEL; t++) {
            float v; int id;
            if (w0 >= w1) { v = w0; id = e0; } else { v = w1; id = e1; }
            #pragma unroll
            for (int o = 16; o; o >>= 1) {
                float ov = __shfl_xor_sync(0xffffffffu, v, o);
                int   oi = __shfl_xor_sync(0xffffffffu, id, o);
                if (ov > v || (ov == v && oi < id)) { v = ov; id = oi; }
            }
            thr = v;
            if (id == e0) { w0 = -INFINITY; h0 = 1.f; }
            if (id == e1) { w1 = -INFINITY; h1 = 1.f; }
        }

        // ---- softmax maxes / sums (exp computed once) ----
        float m1 = wmax(fmaxf(nz0, nz1));
        float m2 = wmax(fmaxf(nz0 + g0, nz1 + g1));
        float m3 = wmax(fmaxf(raw0, raw1));
        float E10 = expf(nz0 - m1),      E11 = expf(nz1 - m1);
        float E20 = expf(nz0 + g0 - m2), E21 = expf(nz1 + g1 - m2);
        float E30 = expf(raw0 - m3),     E31 = expf(raw1 - m3);
        float i1 = 1.f / wsum(E10 + E11);
        float i2 = 1.f / wsum(E20 + E21);
        float i3 = 1.f / wsum(E30 + E31);

        float ms0 = E20 * i2, ms1 = E21 * i2;
        float* om  = out + (size_t)row * NEXP;
        float* orp = out + (size_t)N_TOK * NEXP + (size_t)row * NEXP;
        om[e0]  = (h0 - ms0) + ms0;
        om[e1]  = (h1 - ms1) + ms1;
        orp[e0] = E10 * i1;
        orp[e1] = E11 * i1;

        impa0 += E30 * i3;
        impa1 += E31 * i3;
        float z0 = (thr - raw0) / sd0, z1 = (thr - raw1) / sd1;
        lda0 += 0.5f * (1.f - erff(z0 * INV_SIG_SQRT2));
        lda1 += 0.5f * (1.f - erff(z1 * INV_SIG_SQRT2));
    }

    atomicAdd(&imp_s[e0], impa0);
    atomicAdd(&imp_s[e1], impa1);
    atomicAdd(&load_s[e0], lda0);
    atomicAdd(&load_s[e1], lda1);
    __syncthreads();
    if (tid < 64) {
        atomicAdd(out + 2 * (size_t)N_TOK * NEXP + tid,        imp_s[tid]);
        atomicAdd(out + 2 * (size_t)N_TOK * NEXP + NEXP + tid, load_s[tid]);
    }
}

extern "C" void kernel_launch(void* const* d_in, const int* in_sizes, int n_in,
                              void* d_out, int out_size)
{
    const float* x    = (const float*)d_in[0];
    const float* Wr   = (const float*)d_in[1];
    const float* br   = (const float*)d_in[2];
    const float* Wn   = (const float*)d_in[3];
    const float* bn   = (const float*)d_in[4];
    const float* neps = (const float*)d_in[5];
    const float* gum  = (const float*)d_in[6];
    float* out = (float*)d_out;

    cudaMemsetAsync(out + 2 * (size_t)N_TOK * NEXP, 0, 2 * NEXP * sizeof(float));

    cudaFuncSetAttribute(gemm_kernel,
                         cudaFuncAttributeMaxDynamicSharedMemorySize, SMEM_BYTES);
    gemm_kernel<<<N_TOK / BM, 256, SMEM_BYTES>>>(x, Wr, Wn);

    epi_kernel<<<N_TOK / 64, 256>>>(br, bn, neps, gum, out);
}